// round 16
// baseline (speedup 1.0000x reference)
#include <cuda_runtime.h>
#include <cuda.h>
#include <cuda_fp16.h>
#include <cstdint>

// ============================================================
// y = (clip(round(x/sx)) @ (s0*w0 + s1*w1)^T) * sx + bias
// One folded fp16 weight -> single fp16 mma.sync GEMM.
// R16: R15 (64x64 warp tiles, persistent CTAs, 555.9us) with the
// pipeline deepened back to 4 independent chunk slots (lookahead
// 3 chunks instead of 1 mega) to absorb TMA jitter.
// ============================================================

#define M_ROWS 8192
#define K_DIM  4096
#define N_COLS 4096

#define BM 128
#define BN 256
#define BK 64
#define CHUNKS_PER_TILE 64    // K 4096 / BK
#define NTHREADS 256
#define NCTA 148
#define NTILES ((M_ROWS / BM) * (N_COLS / BN))   // 1024

#define A_STAGE (BM * BK * 2) // 16384 B per chunk
#define B_STAGE (BN * BK * 2) // 32768 B per chunk
#define STAGE_BYTES (A_STAGE + B_STAGE)
#define SMEM_MBAR_FULL(s)  ((s) * 8)          // s = 0..3
#define SMEM_MBAR_EMPTY(s) (32 + (s) * 8)
#define SMEM_A_OFF(c) (1024 + (c) * A_STAGE)              // c = 0..3
#define SMEM_B_OFF(c) (1024 + 4 * A_STAGE + (c) * B_STAGE)
#define SMEM_TOTAL (1024 + 4 * (A_STAGE + B_STAGE))       // 197632

// ---------------- scratch (device globals; no allocs allowed) ----------------
__device__ __align__(1024) __half g_xq[(size_t)M_ROWS * K_DIM];   // 64 MB
__device__ __align__(1024) __half g_wc[(size_t)N_COLS * K_DIM];   // 32 MB [N][K]
__device__ float g_scale_x[M_ROWS];

// ---------------- asm helpers ----------------
__device__ __forceinline__ uint32_t smem_u32(const void* p) {
    uint32_t a;
    asm("{ .reg .u64 t; cvta.to.shared.u64 t, %1; cvt.u32.u64 %0, t; }"
        : "=r"(a) : "l"(p));
    return a;
}

#define MBARRIER_INIT(addr, cnt) \
    asm volatile("mbarrier.init.shared.b64 [%0], %1;" \
                 :: "r"((uint32_t)(addr)), "r"((uint32_t)(cnt)) : "memory")
#define MBARRIER_EXPECT_TX(addr, bytes) \
    asm volatile("mbarrier.arrive.expect_tx.shared.b64 _, [%0], %1;" \
                 :: "r"((uint32_t)(addr)), "r"((uint32_t)(bytes)) : "memory")
#define MBARRIER_ARRIVE(addr) \
    asm volatile("mbarrier.arrive.shared.b64 _, [%0];" \
                 :: "r"((uint32_t)(addr)) : "memory")

#define MBARRIER_WAIT_PARITY(addr, parity) do {                                   \
    uint32_t _m = (uint32_t)(addr); uint32_t _p = (uint32_t)(parity);             \
    uint32_t _done;                                                               \
    asm volatile("{\n\t.reg .pred p;\n\t"                                         \
        "mbarrier.try_wait.parity.acquire.cta.shared::cta.b64 p, [%1], %2;\n\t"   \
        "selp.b32 %0, 1, 0, p;\n\t}"                                              \
        : "=r"(_done) : "r"(_m), "r"(_p) : "memory");                             \
    if (!_done) {                                                                 \
        asm volatile("{\n\t.reg .pred P1;\n\t"                                    \
            "WL_%=:\n\t"                                                          \
            "mbarrier.try_wait.parity.acquire.cta.shared::cta.b64 P1, [%0], %1, 0x989680;\n\t" \
            "@P1 bra.uni WD_%=;\n\t"                                              \
            "bra.uni WL_%=;\n\t"                                                  \
            "WD_%=:\n\t}"                                                         \
            :: "r"(_m), "r"(_p) : "memory");                                      \
    }                                                                             \
} while (0)

#define MBARRIER_WAIT_PARITY_RELAXED(addr, parity) do {                           \
    uint32_t _m = (uint32_t)(addr); uint32_t _p = (uint32_t)(parity);             \
    uint32_t _done;                                                               \
    asm volatile("{\n\t.reg .pred p;\n\t"                                         \
        "mbarrier.try_wait.parity.relaxed.cta.shared::cta.b64 p, [%1], %2, 0x989680;\n\t" \
        "selp.b32 %0, 1, 0, p;\n\t}"                                              \
        : "=r"(_done) : "r"(_m), "r"(_p) : "memory");                             \
    if (!_done) {                                                                 \
        asm volatile("{\n\t.reg .pred P1;\n\t"                                    \
            "WL_%=:\n\t"                                                          \
            "mbarrier.try_wait.parity.relaxed.cta.shared::cta.b64 P1, [%0], %1, 0x989680;\n\t" \
            "@P1 bra.uni WD_%=;\n\t"                                              \
            "bra.uni WL_%=;\n\t"                                                  \
            "WD_%=:\n\t}"                                                         \
            :: "r"(_m), "r"(_p) : "memory");                                      \
    }                                                                             \
} while (0)

#define TMA_LOAD_2D(smem_addr, map_ptr, cx, cy, mbar) \
    asm volatile("cp.async.bulk.tensor.2d.shared::cta.global.tile.mbarrier::complete_tx::bytes " \
                 "[%0], [%1, {%2, %3}], [%4];" \
                 :: "r"((uint32_t)(smem_addr)), "l"(map_ptr), \
                    "r"((int)(cx)), "r"((int)(cy)), "r"((uint32_t)(mbar)) : "memory")

#define FENCE_PROXY_ASYNC() \
    asm volatile("fence.proxy.async.shared::cta;" ::: "memory")

#define LDSM_X4(r0, r1, r2, r3, addr) \
    asm volatile("ldmatrix.sync.aligned.m8n8.x4.shared.b16 {%0,%1,%2,%3}, [%4];" \
                 : "=r"(r0), "=r"(r1), "=r"(r2), "=r"(r3) : "r"(addr))

#define MMA16816(d, a, b) \
    asm volatile("mma.sync.aligned.m16n8k16.row.col.f32.f16.f16.f32 " \
                 "{%0,%1,%2,%3}, {%4,%5,%6,%7}, {%8,%9}, {%0,%1,%2,%3};" \
                 : "+f"((d)[0]), "+f"((d)[1]), "+f"((d)[2]), "+f"((d)[3]) \
                 : "r"((a)[0]), "r"((a)[1]), "r"((a)[2]), "r"((a)[3]), \
                   "r"((b)[0]), "r"((b)[1]))

// ---------------- kernel 1: per-row amax -> softplus scale -> fp16 quantize ----------------
__global__ __launch_bounds__(256) void quantize_kernel(const float* __restrict__ x) {
    int row = blockIdx.x;
    const float4* xr = (const float4*)(x + (size_t)row * K_DIM);
    float4 v[4];
    float amax = 0.f;
#pragma unroll
    for (int i = 0; i < 4; i++) {
        v[i] = __ldcs(&xr[threadIdx.x + i * 256]);   // read-once: streaming
        amax = fmaxf(amax, fmaxf(fmaxf(fabsf(v[i].x), fabsf(v[i].y)),
                                 fmaxf(fabsf(v[i].z), fabsf(v[i].w))));
    }
#pragma unroll
    for (int off = 16; off; off >>= 1)
        amax = fmaxf(amax, __shfl_xor_sync(0xffffffffu, amax, off));
    __shared__ float wmax[8];
    if ((threadIdx.x & 31) == 0) wmax[threadIdx.x >> 5] = amax;
    __syncthreads();
    amax = wmax[0];
#pragma unroll
    for (int i = 1; i < 8; i++) amax = fmaxf(amax, wmax[i]);

    float sp = (amax > 20.f) ? amax : log1pf(expf(amax));   // softplus
    float s = sp * (1.f / 32767.f);
    if (threadIdx.x == 0) g_scale_x[row] = s;
    const float rs = 1.0f / s;   // one divide; 16 multiplies below

    uint2* xq2 = (uint2*)(g_xq + (size_t)row * K_DIM);
#pragma unroll
    for (int i = 0; i < 4; i++) {
        float qx = fminf(fmaxf(rintf(v[i].x * rs), -32768.f), 32767.f);
        float qy = fminf(fmaxf(rintf(v[i].y * rs), -32768.f), 32767.f);
        float qz = fminf(fmaxf(rintf(v[i].z * rs), -32768.f), 32767.f);
        float qw = fminf(fmaxf(rintf(v[i].w * rs), -32768.f), 32767.f);
        __half2 h0 = __floats2half2_rn(qx, qy);
        __half2 h1 = __floats2half2_rn(qz, qw);
        uint2 p;
        p.x = *reinterpret_cast<unsigned*>(&h0);
        p.y = *reinterpret_cast<unsigned*>(&h1);
        xq2[threadIdx.x + i * 256] = p;
    }
}

// ---------------- kernel 2: Wc = s0*w0 + s1*w1 -> fp16, layout [N][K] ----------------
__global__ __launch_bounds__(256) void combine_kernel(const float* __restrict__ w0,
                                                      const float* __restrict__ w1,
                                                      const float* __restrict__ s0,
                                                      const float* __restrict__ s1) {
    const int idx = blockIdx.x * 256 + threadIdx.x;   // grid covers N*K/4 exactly
    const int o = idx >> 10;  // 1024 float4 per output row (K=4096)
    const float a0 = s0[o], a1 = s1[o];
    float4 u = __ldcs(&((const float4*)w0)[idx]);
    float4 v = __ldcs(&((const float4*)w1)[idx]);
    __half2 h0 = __floats2half2_rn(u.x * a0 + v.x * a1, u.y * a0 + v.y * a1);
    __half2 h1 = __floats2half2_rn(u.z * a0 + v.z * a1, u.w * a0 + v.w * a1);
    uint2 p;
    p.x = *reinterpret_cast<unsigned*>(&h0);
    p.y = *reinterpret_cast<unsigned*>(&h1);
    ((uint2*)g_wc)[idx] = p;
}

// ---------------- kernel 3: persistent fp16 mma.sync GEMM, 4-chunk pipeline ----------------
__global__ __launch_bounds__(NTHREADS, 1)
void gemm_kernel(const __grid_constant__ CUtensorMap tma_a,
                 const __grid_constant__ CUtensorMap tma_b,
                 const float* __restrict__ bias, float* __restrict__ out) {
    extern __shared__ __align__(1024) char smem[];
    const uint32_t sb = smem_u32(smem);
    const int tid = threadIdx.x;
    const int lane = tid & 31;
    const int wid = tid >> 5;      // 0..7
    const int wm = wid >> 2;       // 0..1 : 64-row slab
    const int wn = wid & 3;        // 0..3 : 64-col slab
    const int bid = blockIdx.x;    // 0..147

    const int ntiles = (NTILES - bid + NCTA - 1) / NCTA;
    const int C = ntiles * CHUNKS_PER_TILE;   // total chunks for this CTA

    if (tid == 0) {
#pragma unroll
        for (int s = 0; s < 4; s++) {
            MBARRIER_INIT(sb + SMEM_MBAR_FULL(s), 1);
            MBARRIER_INIT(sb + SMEM_MBAR_EMPTY(s), 8);
        }
        FENCE_PROXY_ASYNC();
    }
    __syncthreads();

    // prologue: chunks 0..3 of the first tile into slots 0..3
    if (tid == 0) {
        const int mt0 = bid >> 4, nt0 = bid & 15;
#pragma unroll
        for (int s = 0; s < 4; s++) {
            MBARRIER_EXPECT_TX(sb + SMEM_MBAR_FULL(s), STAGE_BYTES);
            TMA_LOAD_2D(sb + SMEM_A_OFF(s), &tma_a, s * BK, mt0 * BM,
                        sb + SMEM_MBAR_FULL(s));
            TMA_LOAD_2D(sb + SMEM_B_OFF(s), &tma_b, s * BK, nt0 * BN,
                        sb + SMEM_MBAR_FULL(s));
        }
    }

    float acc[4][8][4];
#pragma unroll
    for (int i = 0; i < 4; i++)
#pragma unroll
        for (int j = 0; j < 8; j++)
#pragma unroll
            for (int c = 0; c < 4; c++) acc[i][j][c] = 0.f;

    // per-lane ldmatrix address components (TMA SW128 == chunk ^ (row&7) layout)
    uint32_t rowA[4];
#pragma unroll
    for (int i = 0; i < 4; i++)
        rowA[i] = (uint32_t)((wm * 64 + i * 16 + (lane & 15)) * 128);
    const int hiA = (lane >> 4) & 1;
    const int noff = ((lane >> 4) << 3) | (lane & 7);
    uint32_t rowB[4];
#pragma unroll
    for (int j2 = 0; j2 < 4; j2++)
        rowB[j2] = (uint32_t)((wn * 64 + j2 * 16 + noff) * 128);
    const int hiB = (lane >> 3) & 1;
    const int x7 = lane & 7;

    const int r4 = lane >> 2;
    const int cpair = (lane & 3) * 2;

#pragma unroll 1
    for (int c = 0; c < C; c++) {
        // producer: refill slot freed last iteration with chunk c+3
        if (tid == 0 && c >= 1 && c + 3 < C) {
            const int sp = (c - 1) & 3;     // == (c+3)&3
            const int cn = c + 3;
            const int Tn = bid + (cn >> 6) * NCTA;
            const int mtn = Tn >> 4, ntn = Tn & 15;
            const int lc = cn & 63;
            MBARRIER_WAIT_PARITY_RELAXED(sb + SMEM_MBAR_EMPTY(sp), ((c - 1) >> 2) & 1);
            MBARRIER_EXPECT_TX(sb + SMEM_MBAR_FULL(sp), STAGE_BYTES);
            TMA_LOAD_2D(sb + SMEM_A_OFF(sp), &tma_a, lc * BK, mtn * BM,
                        sb + SMEM_MBAR_FULL(sp));
            TMA_LOAD_2D(sb + SMEM_B_OFF(sp), &tma_b, lc * BK, ntn * BN,
                        sb + SMEM_MBAR_FULL(sp));
        }

        const int s = c & 3;
        MBARRIER_WAIT_PARITY(sb + SMEM_MBAR_FULL(s), (c >> 2) & 1);

        const uint32_t a_base = sb + SMEM_A_OFF(s);
        const uint32_t b_base = sb + SMEM_B_OFF(s);

#pragma unroll
        for (int kk = 0; kk < 4; kk++) {
            const uint32_t cA = (uint32_t)(((kk * 2 + hiA) ^ x7) << 4);
            const uint32_t cB = (uint32_t)(((kk * 2 + hiB) ^ x7) << 4);
            uint32_t a[4][4];
#pragma unroll
            for (int i = 0; i < 4; i++)
                LDSM_X4(a[i][0], a[i][1], a[i][2], a[i][3], a_base + rowA[i] + cA);
            uint32_t b[8][2];
#pragma unroll
            for (int j2 = 0; j2 < 4; j2++)
                LDSM_X4(b[2 * j2][0], b[2 * j2][1], b[2 * j2 + 1][0], b[2 * j2 + 1][1],
                        b_base + rowB[j2] + cB);
            // early release: after the LAST ldmatrix of this chunk, free the slot
            if (kk == 3 && lane == 0)
                MBARRIER_ARRIVE(sb + SMEM_MBAR_EMPTY(s));
#pragma unroll
            for (int i = 0; i < 4; i++)
#pragma unroll
                for (int j = 0; j < 8; j++)
                    MMA16816(acc[i][j], a[i], b[j]);
        }

        // ---- tile boundary: epilogue + acc reset (pipeline keeps flowing) ----
        if ((c & 63) == 63) {
            const int T = bid + (c >> 6) * NCTA;
            const int mt = T >> 4, nt = T & 15;
            const size_t mbase = (size_t)mt * BM + wm * 64;
            const int nbase = nt * BN + wn * 64;

#pragma unroll
            for (int i = 0; i < 4; i++) {
                const size_t row0 = mbase + i * 16 + r4;
                const float sx0 = g_scale_x[row0];
                const float sx1 = g_scale_x[row0 + 8];
                float* o0 = out + row0 * N_COLS + nbase + cpair;
                float* o1 = o0 + (size_t)8 * N_COLS;
#pragma unroll
                for (int j = 0; j < 8; j++) {
                    const float b0 = bias[nbase + j * 8 + cpair];
                    const float b1 = bias[nbase + j * 8 + cpair + 1];
                    float2 v0, v1;
                    v0.x = acc[i][j][0] * sx0 + b0;
                    v0.y = acc[i][j][1] * sx0 + b1;
                    v1.x = acc[i][j][2] * sx1 + b0;
                    v1.y = acc[i][j][3] * sx1 + b1;
                    *(float2*)(o0 + j * 8) = v0;
                    *(float2*)(o1 + j * 8) = v1;
                }
            }
#pragma unroll
            for (int i = 0; i < 4; i++)
#pragma unroll
                for (int j = 0; j < 8; j++)
#pragma unroll
                    for (int c2 = 0; c2 < 4; c2++) acc[i][j][c2] = 0.f;
        }
    }
}

// ---------------- host launch ----------------
typedef CUresult (*PFN_encodeTiled)(
    CUtensorMap*, CUtensorMapDataType, cuuint32_t, void*,
    const cuuint64_t*, const cuuint64_t*, const cuuint32_t*, const cuuint32_t*,
    CUtensorMapInterleave, CUtensorMapSwizzle, CUtensorMapL2promotion,
    CUtensorMapFloatOOBfill);

static PFN_encodeTiled get_encode_fn() {
    static PFN_encodeTiled fn = nullptr;
    if (!fn) {
        void* p = nullptr;
        cudaDriverEntryPointQueryResult st;
        cudaGetDriverEntryPoint("cuTensorMapEncodeTiled", &p,
                                cudaEnableDefault, &st);
        fn = (PFN_encodeTiled)p;
    }
    return fn;
}

extern "C" void kernel_launch(void* const* d_in, const int* in_sizes, int n_in,
                              void* d_out, int out_size) {
    (void)in_sizes; (void)n_in; (void)out_size;
    const float* x    = (const float*)d_in[0];
    const float* w0   = (const float*)d_in[1];
    const float* w1   = (const float*)d_in[2];
    const float* s0   = (const float*)d_in[3];
    const float* s1   = (const float*)d_in[4];
    const float* bias = (const float*)d_in[5];
    float* out = (float*)d_out;

    void* xq_ptr = nullptr;
    void* wc_ptr = nullptr;
    cudaGetSymbolAddress(&xq_ptr, g_xq);
    cudaGetSymbolAddress(&wc_ptr, g_wc);

    PFN_encodeTiled encode = get_encode_fn();

    CUtensorMap tma_a{}, tma_b{};
    {
        cuuint64_t dims[2]    = {K_DIM, M_ROWS};
        cuuint64_t strides[1] = {K_DIM * sizeof(__half)};
        cuuint32_t box[2]     = {BK, BM};   // 64 fp16 = 128B inner box == SW128 atom
        cuuint32_t es[2]      = {1, 1};
        encode(&tma_a, CU_TENSOR_MAP_DATA_TYPE_FLOAT16, 2, xq_ptr,
               dims, strides, box, es,
               CU_TENSOR_MAP_INTERLEAVE_NONE, CU_TENSOR_MAP_SWIZZLE_128B,
               CU_TENSOR_MAP_L2_PROMOTION_L2_128B,
               CU_TENSOR_MAP_FLOAT_OOB_FILL_NONE);
    }
    {
        cuuint64_t dims[2]    = {K_DIM, N_COLS};
        cuuint64_t strides[1] = {K_DIM * sizeof(__half)};
        cuuint32_t box[2]     = {BK, BN};
        cuuint32_t es[2]      = {1, 1};
        encode(&tma_b, CU_TENSOR_MAP_DATA_TYPE_FLOAT16, 2, wc_ptr,
               dims, strides, box, es,
               CU_TENSOR_MAP_INTERLEAVE_NONE, CU_TENSOR_MAP_SWIZZLE_128B,
               CU_TENSOR_MAP_L2_PROMOTION_L2_128B,
               CU_TENSOR_MAP_FLOAT_OOB_FILL_NONE);
    }

    cudaFuncSetAttribute(gemm_kernel, cudaFuncAttributeMaxDynamicSharedMemorySize,
                         SMEM_TOTAL);

    quantize_kernel<<<M_ROWS, 256>>>(x);
    combine_kernel<<<(N_COLS * K_DIM / 4) / 256, 256>>>(w0, w1, s0, s1);  // 16384 blocks
    gemm_kernel<<<NCTA, NTHREADS, SMEM_TOTAL>>>(tma_a, tma_b, bias, out);
}

// round 17
// speedup vs baseline: 1.0392x; 1.0392x over previous
#include <cuda_runtime.h>
#include <cuda.h>
#include <cuda_fp16.h>
#include <cstdint>

// ============================================================
// y = (clip(round(x/sx)) @ (s0*w0 + s1*w1)^T) * sx + bias
// One folded fp16 weight -> single fp16 mma.sync GEMM.
// R17 = R15 verbatim (best: 555.9us). R16's finer-grained 4-slot
// pipeline regressed (+21.7us: 2x barrier events/tile). Final
// form: 64x64 warp tiles (min LDSM/MMA), 2 mega-stage TMA
// pipeline (min barrier events), persistent CTAs (no waves).
// GEMM ~505us = 94.6% of HMMA issue floor; prep at DRAM roofline.
// ============================================================

#define M_ROWS 8192
#define K_DIM  4096
#define N_COLS 4096

#define BM 128
#define BN 256
#define BK 64
#define MEGAS_PER_TILE 32     // 32 megas of 2 chunks (BK=64) = K 4096
#define NTHREADS 256
#define NCTA 148
#define NTILES ((M_ROWS / BM) * (N_COLS / BN))   // 1024

#define A_STAGE (BM * BK * 2) // 16384 B per chunk
#define B_STAGE (BN * BK * 2) // 32768 B per chunk
#define STAGE_BYTES (A_STAGE + B_STAGE)
#define MEGA_BYTES (2 * STAGE_BYTES)          // 98304
#define SMEM_MBAR_FULL(m)  ((m) * 8)          // m = 0,1
#define SMEM_MBAR_EMPTY(m) (16 + (m) * 8)
#define SMEM_A_OFF(c) (1024 + (c) * A_STAGE)              // c = 0..3
#define SMEM_B_OFF(c) (1024 + 4 * A_STAGE + (c) * B_STAGE)
#define SMEM_TOTAL (1024 + 4 * (A_STAGE + B_STAGE))       // 197632

// ---------------- scratch (device globals; no allocs allowed) ----------------
__device__ __align__(1024) __half g_xq[(size_t)M_ROWS * K_DIM];   // 64 MB
__device__ __align__(1024) __half g_wc[(size_t)N_COLS * K_DIM];   // 32 MB [N][K]
__device__ float g_scale_x[M_ROWS];

// ---------------- asm helpers ----------------
__device__ __forceinline__ uint32_t smem_u32(const void* p) {
    uint32_t a;
    asm("{ .reg .u64 t; cvta.to.shared.u64 t, %1; cvt.u32.u64 %0, t; }"
        : "=r"(a) : "l"(p));
    return a;
}

#define MBARRIER_INIT(addr, cnt) \
    asm volatile("mbarrier.init.shared.b64 [%0], %1;" \
                 :: "r"((uint32_t)(addr)), "r"((uint32_t)(cnt)) : "memory")
#define MBARRIER_EXPECT_TX(addr, bytes) \
    asm volatile("mbarrier.arrive.expect_tx.shared.b64 _, [%0], %1;" \
                 :: "r"((uint32_t)(addr)), "r"((uint32_t)(bytes)) : "memory")
#define MBARRIER_ARRIVE(addr) \
    asm volatile("mbarrier.arrive.shared.b64 _, [%0];" \
                 :: "r"((uint32_t)(addr)) : "memory")

#define MBARRIER_WAIT_PARITY(addr, parity) do {                                   \
    uint32_t _m = (uint32_t)(addr); uint32_t _p = (uint32_t)(parity);             \
    uint32_t _done;                                                               \
    asm volatile("{\n\t.reg .pred p;\n\t"                                         \
        "mbarrier.try_wait.parity.acquire.cta.shared::cta.b64 p, [%1], %2;\n\t"   \
        "selp.b32 %0, 1, 0, p;\n\t}"                                              \
        : "=r"(_done) : "r"(_m), "r"(_p) : "memory");                             \
    if (!_done) {                                                                 \
        asm volatile("{\n\t.reg .pred P1;\n\t"                                    \
            "WL_%=:\n\t"                                                          \
            "mbarrier.try_wait.parity.acquire.cta.shared::cta.b64 P1, [%0], %1, 0x989680;\n\t" \
            "@P1 bra.uni WD_%=;\n\t"                                              \
            "bra.uni WL_%=;\n\t"                                                  \
            "WD_%=:\n\t}"                                                         \
            :: "r"(_m), "r"(_p) : "memory");                                      \
    }                                                                             \
} while (0)

#define MBARRIER_WAIT_PARITY_RELAXED(addr, parity) do {                           \
    uint32_t _m = (uint32_t)(addr); uint32_t _p = (uint32_t)(parity);             \
    uint32_t _done;                                                               \
    asm volatile("{\n\t.reg .pred p;\n\t"                                         \
        "mbarrier.try_wait.parity.relaxed.cta.shared::cta.b64 p, [%1], %2, 0x989680;\n\t" \
        "selp.b32 %0, 1, 0, p;\n\t}"                                              \
        : "=r"(_done) : "r"(_m), "r"(_p) : "memory");                             \
    if (!_done) {                                                                 \
        asm volatile("{\n\t.reg .pred P1;\n\t"                                    \
            "WL_%=:\n\t"                                                          \
            "mbarrier.try_wait.parity.relaxed.cta.shared::cta.b64 P1, [%0], %1, 0x989680;\n\t" \
            "@P1 bra.uni WD_%=;\n\t"                                              \
            "bra.uni WL_%=;\n\t"                                                  \
            "WD_%=:\n\t}"                                                         \
            :: "r"(_m), "r"(_p) : "memory");                                      \
    }                                                                             \
} while (0)

#define TMA_LOAD_2D(smem_addr, map_ptr, cx, cy, mbar) \
    asm volatile("cp.async.bulk.tensor.2d.shared::cta.global.tile.mbarrier::complete_tx::bytes " \
                 "[%0], [%1, {%2, %3}], [%4];" \
                 :: "r"((uint32_t)(smem_addr)), "l"(map_ptr), \
                    "r"((int)(cx)), "r"((int)(cy)), "r"((uint32_t)(mbar)) : "memory")

#define FENCE_PROXY_ASYNC() \
    asm volatile("fence.proxy.async.shared::cta;" ::: "memory")

#define LDSM_X4(r0, r1, r2, r3, addr) \
    asm volatile("ldmatrix.sync.aligned.m8n8.x4.shared.b16 {%0,%1,%2,%3}, [%4];" \
                 : "=r"(r0), "=r"(r1), "=r"(r2), "=r"(r3) : "r"(addr))

#define MMA16816(d, a, b) \
    asm volatile("mma.sync.aligned.m16n8k16.row.col.f32.f16.f16.f32 " \
                 "{%0,%1,%2,%3}, {%4,%5,%6,%7}, {%8,%9}, {%0,%1,%2,%3};" \
                 : "+f"((d)[0]), "+f"((d)[1]), "+f"((d)[2]), "+f"((d)[3]) \
                 : "r"((a)[0]), "r"((a)[1]), "r"((a)[2]), "r"((a)[3]), \
                   "r"((b)[0]), "r"((b)[1]))

// ---------------- kernel 1: per-row amax -> softplus scale -> fp16 quantize ----------------
__global__ __launch_bounds__(256) void quantize_kernel(const float* __restrict__ x) {
    int row = blockIdx.x;
    const float4* xr = (const float4*)(x + (size_t)row * K_DIM);
    float4 v[4];
    float amax = 0.f;
#pragma unroll
    for (int i = 0; i < 4; i++) {
        v[i] = __ldcs(&xr[threadIdx.x + i * 256]);   // read-once: streaming
        amax = fmaxf(amax, fmaxf(fmaxf(fabsf(v[i].x), fabsf(v[i].y)),
                                 fmaxf(fabsf(v[i].z), fabsf(v[i].w))));
    }
#pragma unroll
    for (int off = 16; off; off >>= 1)
        amax = fmaxf(amax, __shfl_xor_sync(0xffffffffu, amax, off));
    __shared__ float wmax[8];
    if ((threadIdx.x & 31) == 0) wmax[threadIdx.x >> 5] = amax;
    __syncthreads();
    amax = wmax[0];
#pragma unroll
    for (int i = 1; i < 8; i++) amax = fmaxf(amax, wmax[i]);

    float sp = (amax > 20.f) ? amax : log1pf(expf(amax));   // softplus
    float s = sp * (1.f / 32767.f);
    if (threadIdx.x == 0) g_scale_x[row] = s;
    const float rs = 1.0f / s;   // one divide; 16 multiplies below

    uint2* xq2 = (uint2*)(g_xq + (size_t)row * K_DIM);
#pragma unroll
    for (int i = 0; i < 4; i++) {
        float qx = fminf(fmaxf(rintf(v[i].x * rs), -32768.f), 32767.f);
        float qy = fminf(fmaxf(rintf(v[i].y * rs), -32768.f), 32767.f);
        float qz = fminf(fmaxf(rintf(v[i].z * rs), -32768.f), 32767.f);
        float qw = fminf(fmaxf(rintf(v[i].w * rs), -32768.f), 32767.f);
        __half2 h0 = __floats2half2_rn(qx, qy);
        __half2 h1 = __floats2half2_rn(qz, qw);
        uint2 p;
        p.x = *reinterpret_cast<unsigned*>(&h0);
        p.y = *reinterpret_cast<unsigned*>(&h1);
        xq2[threadIdx.x + i * 256] = p;
    }
}

// ---------------- kernel 2: Wc = s0*w0 + s1*w1 -> fp16, layout [N][K] ----------------
__global__ __launch_bounds__(256) void combine_kernel(const float* __restrict__ w0,
                                                      const float* __restrict__ w1,
                                                      const float* __restrict__ s0,
                                                      const float* __restrict__ s1) {
    const int idx = blockIdx.x * 256 + threadIdx.x;   // grid covers N*K/4 exactly
    const int o = idx >> 10;  // 1024 float4 per output row (K=4096)
    const float a0 = s0[o], a1 = s1[o];
    float4 u = __ldcs(&((const float4*)w0)[idx]);
    float4 v = __ldcs(&((const float4*)w1)[idx]);
    __half2 h0 = __floats2half2_rn(u.x * a0 + v.x * a1, u.y * a0 + v.y * a1);
    __half2 h1 = __floats2half2_rn(u.z * a0 + v.z * a1, u.w * a0 + v.w * a1);
    uint2 p;
    p.x = *reinterpret_cast<unsigned*>(&h0);
    p.y = *reinterpret_cast<unsigned*>(&h1);
    ((uint2*)g_wc)[idx] = p;
}

// ---------------- kernel 3: persistent fp16 mma.sync GEMM, 64x64 warp tiles ----------------
__global__ __launch_bounds__(NTHREADS, 1)
void gemm_kernel(const __grid_constant__ CUtensorMap tma_a,
                 const __grid_constant__ CUtensorMap tma_b,
                 const float* __restrict__ bias, float* __restrict__ out) {
    extern __shared__ __align__(1024) char smem[];
    const uint32_t sb = smem_u32(smem);
    const int tid = threadIdx.x;
    const int lane = tid & 31;
    const int wid = tid >> 5;      // 0..7
    const int wm = wid >> 2;       // 0..1 : 64-row slab
    const int wn = wid & 3;        // 0..3 : 64-col slab
    const int bid = blockIdx.x;    // 0..147

    const int ntiles = (NTILES - bid + NCTA - 1) / NCTA;
    const int G = ntiles * MEGAS_PER_TILE;   // total megas for this CTA

    if (tid == 0) {
#pragma unroll
        for (int m = 0; m < 2; m++) {
            MBARRIER_INIT(sb + SMEM_MBAR_FULL(m), 1);
            MBARRIER_INIT(sb + SMEM_MBAR_EMPTY(m), 8);
        }
        FENCE_PROXY_ASYNC();
    }
    __syncthreads();

    // prologue: load megas 0 and 1 (first tile, chunks 0..3)
    if (tid == 0) {
        const int T0 = bid;
        const int mt0 = T0 >> 4, nt0 = T0 & 15;
#pragma unroll
        for (int m = 0; m < 2; m++) {
            MBARRIER_EXPECT_TX(sb + SMEM_MBAR_FULL(m), MEGA_BYTES);
#pragma unroll
            for (int c = 0; c < 2; c++) {
                const int slot = 2 * m + c;
                TMA_LOAD_2D(sb + SMEM_A_OFF(slot), &tma_a, slot * BK, mt0 * BM,
                            sb + SMEM_MBAR_FULL(m));
                TMA_LOAD_2D(sb + SMEM_B_OFF(slot), &tma_b, slot * BK, nt0 * BN,
                            sb + SMEM_MBAR_FULL(m));
            }
        }
    }

    float acc[4][8][4];
#pragma unroll
    for (int i = 0; i < 4; i++)
#pragma unroll
        for (int j = 0; j < 8; j++)
#pragma unroll
            for (int c = 0; c < 4; c++) acc[i][j][c] = 0.f;

    // per-lane ldmatrix address components (TMA SW128 == chunk ^ (row&7) layout)
    // A x4 (m16k16): lanes 0-7 m0-7(kLo), 8-15 m8-15(kLo), 16-23 m0-7(kHi), 24-31 m8-15(kHi)
    uint32_t rowA[4];
#pragma unroll
    for (int i = 0; i < 4; i++)
        rowA[i] = (uint32_t)((wm * 64 + i * 16 + (lane & 15)) * 128);
    const int hiA = (lane >> 4) & 1;
    // B x4 (n16k16): lanes 0-7 n0-7(kLo), 8-15 n0-7(kHi), 16-23 n8-15(kLo), 24-31 n8-15(kHi)
    const int noff = ((lane >> 4) << 3) | (lane & 7);
    uint32_t rowB[4];
#pragma unroll
    for (int j2 = 0; j2 < 4; j2++)
        rowB[j2] = (uint32_t)((wn * 64 + j2 * 16 + noff) * 128);
    const int hiB = (lane >> 3) & 1;
    const int x7 = lane & 7;

    const int r4 = lane >> 2;
    const int cpair = (lane & 3) * 2;

#pragma unroll 1
    for (int g = 0; g < G; g++) {
        // producer: refill mega g+1 (slot freed by consumption of mega g-1)
        if (tid == 0 && g >= 1 && g + 1 < G) {
            const int gm = g + 1;
            const int mp = gm & 1;
            const int Tn = bid + (gm >> 5) * NCTA;
            const int mtn = Tn >> 4, ntn = Tn & 15;
            const int lm = gm & 31;                  // local mega in its tile
            MBARRIER_WAIT_PARITY_RELAXED(sb + SMEM_MBAR_EMPTY(mp), ((g - 1) >> 1) & 1);
            MBARRIER_EXPECT_TX(sb + SMEM_MBAR_FULL(mp), MEGA_BYTES);
#pragma unroll
            for (int c = 0; c < 2; c++) {
                const int slot = 2 * mp + c;
                const int chunk = 2 * lm + c;
                TMA_LOAD_2D(sb + SMEM_A_OFF(slot), &tma_a, chunk * BK, mtn * BM,
                            sb + SMEM_MBAR_FULL(mp));
                TMA_LOAD_2D(sb + SMEM_B_OFF(slot), &tma_b, chunk * BK, ntn * BN,
                            sb + SMEM_MBAR_FULL(mp));
            }
        }

        const int m = g & 1;
        MBARRIER_WAIT_PARITY(sb + SMEM_MBAR_FULL(m), (g >> 1) & 1);

#pragma unroll
        for (int c = 0; c < 2; c++) {
            const uint32_t a_base = sb + SMEM_A_OFF(2 * m + c);
            const uint32_t b_base = sb + SMEM_B_OFF(2 * m + c);
#pragma unroll
            for (int kk = 0; kk < 4; kk++) {
                const uint32_t cA = (uint32_t)(((kk * 2 + hiA) ^ x7) << 4);
                const uint32_t cB = (uint32_t)(((kk * 2 + hiB) ^ x7) << 4);
                uint32_t a[4][4];
#pragma unroll
                for (int i = 0; i < 4; i++)
                    LDSM_X4(a[i][0], a[i][1], a[i][2], a[i][3], a_base + rowA[i] + cA);
                uint32_t b[8][2];
#pragma unroll
                for (int j2 = 0; j2 < 4; j2++)
                    LDSM_X4(b[2 * j2][0], b[2 * j2][1], b[2 * j2 + 1][0], b[2 * j2 + 1][1],
                            b_base + rowB[j2] + cB);
                // early release: after the LAST ldmatrix of this mega, free both slots
                if (c == 1 && kk == 3 && lane == 0)
                    MBARRIER_ARRIVE(sb + SMEM_MBAR_EMPTY(m));
#pragma unroll
                for (int i = 0; i < 4; i++)
#pragma unroll
                    for (int j = 0; j < 8; j++)
                        MMA16816(acc[i][j], a[i], b[j]);
            }
        }

        // ---- tile boundary: epilogue + acc reset (pipeline keeps flowing) ----
        if ((g & 31) == 31) {
            const int T = bid + (g >> 5) * NCTA;
            const int mt = T >> 4, nt = T & 15;
            const size_t mbase = (size_t)mt * BM + wm * 64;
            const int nbase = nt * BN + wn * 64;

#pragma unroll
            for (int i = 0; i < 4; i++) {
                const size_t row0 = mbase + i * 16 + r4;
                const float sx0 = g_scale_x[row0];
                const float sx1 = g_scale_x[row0 + 8];
                float* o0 = out + row0 * N_COLS + nbase + cpair;
                float* o1 = o0 + (size_t)8 * N_COLS;
#pragma unroll
                for (int j = 0; j < 8; j++) {
                    const float b0 = bias[nbase + j * 8 + cpair];
                    const float b1 = bias[nbase + j * 8 + cpair + 1];
                    float2 v0, v1;
                    v0.x = acc[i][j][0] * sx0 + b0;
                    v0.y = acc[i][j][1] * sx0 + b1;
                    v1.x = acc[i][j][2] * sx1 + b0;
                    v1.y = acc[i][j][3] * sx1 + b1;
                    *(float2*)(o0 + j * 8) = v0;
                    *(float2*)(o1 + j * 8) = v1;
                }
            }
#pragma unroll
            for (int i = 0; i < 4; i++)
#pragma unroll
                for (int j = 0; j < 8; j++)
#pragma unroll
                    for (int c2 = 0; c2 < 4; c2++) acc[i][j][c2] = 0.f;
        }
    }
}

// ---------------- host launch ----------------
typedef CUresult (*PFN_encodeTiled)(
    CUtensorMap*, CUtensorMapDataType, cuuint32_t, void*,
    const cuuint64_t*, const cuuint64_t*, const cuuint32_t*, const cuuint32_t*,
    CUtensorMapInterleave, CUtensorMapSwizzle, CUtensorMapL2promotion,
    CUtensorMapFloatOOBfill);

static PFN_encodeTiled get_encode_fn() {
    static PFN_encodeTiled fn = nullptr;
    if (!fn) {
        void* p = nullptr;
        cudaDriverEntryPointQueryResult st;
        cudaGetDriverEntryPoint("cuTensorMapEncodeTiled", &p,
                                cudaEnableDefault, &st);
        fn = (PFN_encodeTiled)p;
    }
    return fn;
}

extern "C" void kernel_launch(void* const* d_in, const int* in_sizes, int n_in,
                              void* d_out, int out_size) {
    (void)in_sizes; (void)n_in; (void)out_size;
    const float* x    = (const float*)d_in[0];
    const float* w0   = (const float*)d_in[1];
    const float* w1   = (const float*)d_in[2];
    const float* s0   = (const float*)d_in[3];
    const float* s1   = (const float*)d_in[4];
    const float* bias = (const float*)d_in[5];
    float* out = (float*)d_out;

    void* xq_ptr = nullptr;
    void* wc_ptr = nullptr;
    cudaGetSymbolAddress(&xq_ptr, g_xq);
    cudaGetSymbolAddress(&wc_ptr, g_wc);

    PFN_encodeTiled encode = get_encode_fn();

    CUtensorMap tma_a{}, tma_b{};
    {
        cuuint64_t dims[2]    = {K_DIM, M_ROWS};
        cuuint64_t strides[1] = {K_DIM * sizeof(__half)};
        cuuint32_t box[2]     = {BK, BM};   // 64 fp16 = 128B inner box == SW128 atom
        cuuint32_t es[2]      = {1, 1};
        encode(&tma_a, CU_TENSOR_MAP_DATA_TYPE_FLOAT16, 2, xq_ptr,
               dims, strides, box, es,
               CU_TENSOR_MAP_INTERLEAVE_NONE, CU_TENSOR_MAP_SWIZZLE_128B,
               CU_TENSOR_MAP_L2_PROMOTION_L2_128B,
               CU_TENSOR_MAP_FLOAT_OOB_FILL_NONE);
    }
    {
        cuuint64_t dims[2]    = {K_DIM, N_COLS};
        cuuint64_t strides[1] = {K_DIM * sizeof(__half)};
        cuuint32_t box[2]     = {BK, BN};
        cuuint32_t es[2]      = {1, 1};
        encode(&tma_b, CU_TENSOR_MAP_DATA_TYPE_FLOAT16, 2, wc_ptr,
               dims, strides, box, es,
               CU_TENSOR_MAP_INTERLEAVE_NONE, CU_TENSOR_MAP_SWIZZLE_128B,
               CU_TENSOR_MAP_L2_PROMOTION_L2_128B,
               CU_TENSOR_MAP_FLOAT_OOB_FILL_NONE);
    }

    cudaFuncSetAttribute(gemm_kernel, cudaFuncAttributeMaxDynamicSharedMemorySize,
                         SMEM_TOTAL);

    quantize_kernel<<<M_ROWS, 256>>>(x);
    combine_kernel<<<(N_COLS * K_DIM / 4) / 256, 256>>>(w0, w1, s0, s1);  // 16384 blocks
    gemm_kernel<<<NCTA, NTHREADS, SMEM_TOTAL>>>(tma_a, tma_b, bias, out);
}